// round 15
// baseline (speedup 1.0000x reference)
#include <cuda_runtime.h>
#include <cuda_bf16.h>
#include <cuda_fp16.h>

// GCN 2-layer forward, pull-based aggregation.
// CSR build fused into ONE persistent kernel (grid barrier, 148 co-resident blocks).
//   t1h = fp16( dinv[i] * (x @ W1) )             [tf32 tensor-core GEMM]
//   r   = relu(dinv[i] * (t1h[i] + sum t1h[src]) + b1)   [fp32 accum]
//   t2  = dinv[i] * (r @ W2)                     [tf32 tensor-core GEMM, fp32]
//   out = dinv[i] * (t2[i] + sum t2[src]) + b2

#define MAXN 50000
#define MAXE 800000
#define C1 128
#define C2 64

#define CSR_BLOCKS 148
#define CSR_THREADS 1024

__device__ int    g_is64;
__device__ int    g_cnt[MAXN];
__device__ int    g_off[MAXN + 1];
__device__ int    g_cur[MAXN];
__device__ int    g_srcl[MAXE];
__device__ int    g_part[64];
__device__ float  g_dinv[MAXN];
__device__ __half g_t1h[MAXN * C1];
__device__ float  g_r[MAXN * C1];
__device__ float  g_t2[MAXN * C2];

// grid barrier state (persists across launches; gen is monotonic)
__device__ int          g_bar_cnt = 0;
__device__ volatile int g_bar_gen = 0;

__device__ __forceinline__ void grid_barrier() {
    __syncthreads();
    if (threadIdx.x == 0) {
        __threadfence();
        int gen = g_bar_gen;
        if (atomicAdd(&g_bar_cnt, 1) == (int)gridDim.x - 1) {
            g_bar_cnt = 0;
            __threadfence();
            g_bar_gen = gen + 1;
        } else {
            while (g_bar_gen == gen) { }
        }
        __threadfence();
    }
    __syncthreads();
}

__device__ __forceinline__ int load_edge(const void* ei, long long idx, int is64) {
    if (is64) return (int)((const long long*)ei)[idx];
    return ((const int*)ei)[idx];
}

// ---------------------------------------------------------------------------
// Fused CSR build: zero+detect | count | chunk-scan | partial-scan | apply | bucket
__global__ __launch_bounds__(CSR_THREADS) void k_csr(const void* ei, int n, long long E) {
    __shared__ int s[CSR_THREADS];
    __shared__ int sp[64];

    const int tid   = blockIdx.x * CSR_THREADS + threadIdx.x;
    const int ttot  = CSR_BLOCKS * CSR_THREADS;   // 151552
    const int ltid  = threadIdx.x;

    // ---- phase 0: zero counters + dtype detect ----
    for (int i = tid; i < n; i += ttot) g_cnt[i] = 0;
    if (tid == 0) {
        const unsigned long long* p = (const unsigned long long*)ei;
        long long cnt = E < 64 ? E : 64;
        int ok64 = 1;
        for (long long k = 0; k < cnt; k++) {
            if (p[k] >= (unsigned long long)n) { ok64 = 0; break; }
        }
        g_is64 = ok64;
    }
    grid_barrier();
    const int is64 = g_is64;

    // ---- phase 1: count in-degrees ----
    for (long long e = tid; e < E; e += ttot) {
        int d = load_edge(ei, E + e, is64);
        atomicAdd(&g_cnt[d], 1);
    }
    grid_barrier();

    // ---- phase 2a: per-chunk (1024) exclusive scan; first nch blocks ----
    const int nch = (n + CSR_THREADS - 1) / CSR_THREADS;   // 49
    if ((int)blockIdx.x < nch) {
        int gid = blockIdx.x * CSR_THREADS + ltid;
        int v = (gid < n) ? g_cnt[gid] : 0;
        s[ltid] = v;
        __syncthreads();
#pragma unroll
        for (int o = 1; o < CSR_THREADS; o <<= 1) {
            int t = (ltid >= o) ? s[ltid - o] : 0;
            __syncthreads();
            s[ltid] += t;
            __syncthreads();
        }
        if (gid < n) g_off[gid] = s[ltid] - v;            // exclusive within chunk
        if (ltid == CSR_THREADS - 1) g_part[blockIdx.x] = s[ltid];
    }
    grid_barrier();

    // ---- phase 2b: block 0 scans chunk partials (64-wide, parallel) ----
    if (blockIdx.x == 0) {
        int v0 = 0;
        if (ltid < 64) {
            v0 = (ltid < nch) ? g_part[ltid] : 0;
            sp[ltid] = v0;
        }
        __syncthreads();
#pragma unroll
        for (int o = 1; o < 64; o <<= 1) {
            int t = (ltid < 64 && ltid >= o) ? sp[ltid - o] : 0;
            __syncthreads();
            if (ltid < 64) sp[ltid] += t;
            __syncthreads();
        }
        if (ltid < 64) g_part[ltid] = sp[ltid] - v0;      // exclusive chunk offsets
    }
    grid_barrier();

    // ---- phase 2c: apply offsets, init cursors, dinv ----
    for (int i = tid; i < n; i += ttot) {
        int off = g_off[i] + g_part[i >> 10];
        g_off[i] = off;
        g_cur[i] = off;
        g_dinv[i] = rsqrtf((float)(g_cnt[i] + 1));
    }
    if (tid == 0) g_off[n] = (int)E;
    grid_barrier();

    // ---- phase 3: bucket edges by dst ----
    for (long long e = tid; e < E; e += ttot) {
        int src = load_edge(ei, e, is64);
        int dst = load_edge(ei, E + e, is64);
        int pos = atomicAdd(&g_cur[dst], 1);
        g_srcl[pos] = src;
    }
}

// ---------------------------------------------------------------------------
// tf32 tensor-core GEMM: C[m][c] = dinv[m] * sum_k A[m][k] * W[k][c]
// HALF_OUT: store __half (t1h), else float (t2).
__device__ __forceinline__ unsigned f2tf32(float f) {
    unsigned u;
    asm("cvt.rna.tf32.f32 %0, %1;" : "=r"(u) : "f"(f));
    return u;
}

template <int NC, bool HALF_OUT>
__global__ __launch_bounds__(256) void k_gemm_tf32(
    const float* __restrict__ A, const float* __restrict__ W,
    void* __restrict__ Cout, int M)
{
    constexpr int K   = 128;
    constexpr int BM  = 128;
    constexpr int BK  = 32;
    constexpr int PA  = BK + 4;
    constexpr int PB  = NC + 4;
    constexpr int NF  = NC / 16;

    __shared__ unsigned As[BM * PA];
    __shared__ unsigned Bs[BK * PB];

    int tid  = threadIdx.x;
    int wid  = tid >> 5;
    int lane = tid & 31;
    int wm   = wid >> 1;
    int wn   = wid & 1;
    int g    = lane >> 2;
    int t    = lane & 3;
    int rowBase = blockIdx.x * BM;

    float acc[2][NF][4];
#pragma unroll
    for (int mf = 0; mf < 2; mf++)
#pragma unroll
        for (int nf = 0; nf < NF; nf++)
#pragma unroll
            for (int i = 0; i < 4; i++) acc[mf][nf][i] = 0.0f;

    for (int kc = 0; kc < K; kc += BK) {
#pragma unroll
        for (int it = 0; it < (BM * BK / 4) / 256; it++) {
            int idx = tid + it * 256;
            int row = idx >> 3;
            int c4  = (idx & 7) * 4;
            int gr  = rowBase + row;
            float4 av = make_float4(0.f, 0.f, 0.f, 0.f);
            if (gr < M) av = *(const float4*)&A[(long long)gr * K + kc + c4];
            unsigned* dst = &As[row * PA + c4];
            dst[0] = f2tf32(av.x); dst[1] = f2tf32(av.y);
            dst[2] = f2tf32(av.z); dst[3] = f2tf32(av.w);
        }
#pragma unroll
        for (int it = 0; it < (BK * NC / 4) / 256; it++) {
            int idx = tid + it * 256;
            int row = idx / (NC / 4);
            int c4  = (idx % (NC / 4)) * 4;
            float4 bv = *(const float4*)&W[(kc + row) * NC + c4];
            unsigned* dst = &Bs[row * PB + c4];
            dst[0] = f2tf32(bv.x); dst[1] = f2tf32(bv.y);
            dst[2] = f2tf32(bv.z); dst[3] = f2tf32(bv.w);
        }
        __syncthreads();

#pragma unroll
        for (int kk = 0; kk < BK; kk += 8) {
            unsigned a[2][4];
#pragma unroll
            for (int mf = 0; mf < 2; mf++) {
                int r0 = wm * 32 + mf * 16;
                a[mf][0] = As[(r0 + g)     * PA + kk + t];
                a[mf][1] = As[(r0 + g + 8) * PA + kk + t];
                a[mf][2] = As[(r0 + g)     * PA + kk + t + 4];
                a[mf][3] = As[(r0 + g + 8) * PA + kk + t + 4];
            }
            unsigned b[NF][2];
#pragma unroll
            for (int nf = 0; nf < NF; nf++) {
                int c0 = wn * NF * 8 + nf * 8 + g;
                b[nf][0] = Bs[(kk + t)     * PB + c0];
                b[nf][1] = Bs[(kk + t + 4) * PB + c0];
            }
#pragma unroll
            for (int mf = 0; mf < 2; mf++)
#pragma unroll
                for (int nf = 0; nf < NF; nf++) {
                    asm volatile(
                        "mma.sync.aligned.m16n8k8.row.col.f32.tf32.tf32.f32 "
                        "{%0,%1,%2,%3}, {%4,%5,%6,%7}, {%8,%9}, {%0,%1,%2,%3};\n"
                        : "+f"(acc[mf][nf][0]), "+f"(acc[mf][nf][1]),
                          "+f"(acc[mf][nf][2]), "+f"(acc[mf][nf][3])
                        : "r"(a[mf][0]), "r"(a[mf][1]), "r"(a[mf][2]), "r"(a[mf][3]),
                          "r"(b[nf][0]), "r"(b[nf][1]));
                }
        }
        __syncthreads();
    }

#pragma unroll
    for (int mf = 0; mf < 2; mf++) {
        int r0 = rowBase + wm * 32 + mf * 16 + g;
        int r1 = r0 + 8;
        float d0 = (r0 < M) ? g_dinv[r0] : 0.f;
        float d1 = (r1 < M) ? g_dinv[r1] : 0.f;
#pragma unroll
        for (int nf = 0; nf < NF; nf++) {
            int col = wn * NF * 8 + nf * 8 + 2 * t;
            if (HALF_OUT) {
                __half* C = (__half*)Cout;
                if (r0 < M) {
                    __half2 h0 = __floats2half2_rn(d0 * acc[mf][nf][0], d0 * acc[mf][nf][1]);
                    *(__half2*)&C[(long long)r0 * NC + col] = h0;
                }
                if (r1 < M) {
                    __half2 h1 = __floats2half2_rn(d1 * acc[mf][nf][2], d1 * acc[mf][nf][3]);
                    *(__half2*)&C[(long long)r1 * NC + col] = h1;
                }
            } else {
                float* C = (float*)Cout;
                if (r0 < M) {
                    float2 v0 = make_float2(d0 * acc[mf][nf][0], d0 * acc[mf][nf][1]);
                    *(float2*)&C[(long long)r0 * NC + col] = v0;
                }
                if (r1 < M) {
                    float2 v1 = make_float2(d1 * acc[mf][nf][2], d1 * acc[mf][nf][3]);
                    *(float2*)&C[(long long)r1 * NC + col] = v1;
                }
            }
        }
    }
}

// ---------------------------------------------------------------------------
// Pull layer 1: warp per node, 128 fp16 channels (uint2/lane), serial loop.
__global__ __launch_bounds__(256) void k_pull1(const float* __restrict__ b1, int n) {
    int w = (blockIdx.x * blockDim.x + threadIdx.x) >> 5;
    int lane = threadIdx.x & 31;
    if (w >= n) return;
    const uint2* t1v = (const uint2*)g_t1h;

    uint2 sv = t1v[(long long)w * 32 + lane];
    float2 f0 = __half22float2(*(__half2*)&sv.x);
    float2 f1 = __half22float2(*(__half2*)&sv.y);
    float4 acc = make_float4(f0.x, f0.y, f1.x, f1.y);

    int e0 = g_off[w], e1 = g_off[w + 1];
    for (int e = e0; e < e1; e++) {
        int s = g_srcl[e];
        uint2 v = t1v[(long long)s * 32 + lane];
        float2 a = __half22float2(*(__half2*)&v.x);
        float2 b = __half22float2(*(__half2*)&v.y);
        acc.x += a.x; acc.y += a.y; acc.z += b.x; acc.w += b.y;
    }
    float di = g_dinv[w];
    float4 bb = ((const float4*)b1)[lane];
    float4 r;
    r.x = fmaxf(fmaf(di, acc.x, bb.x), 0.0f);
    r.y = fmaxf(fmaf(di, acc.y, bb.y), 0.0f);
    r.z = fmaxf(fmaf(di, acc.z, bb.z), 0.0f);
    r.w = fmaxf(fmaf(di, acc.w, bb.w), 0.0f);
    ((float4*)g_r)[(long long)w * 32 + lane] = r;
}

// Pull layer 2: warp per node, 64 fp32 channels (float2/lane), serial loop.
__global__ __launch_bounds__(256) void k_pull2(const float* __restrict__ b2,
                                               float* __restrict__ out, int n) {
    int w = (blockIdx.x * blockDim.x + threadIdx.x) >> 5;
    int lane = threadIdx.x & 31;
    if (w >= n) return;
    const float2* t2v = (const float2*)g_t2;
    float2 acc = t2v[(long long)w * 32 + lane];
    int e0 = g_off[w], e1 = g_off[w + 1];
    for (int e = e0; e < e1; e++) {
        int s = g_srcl[e];
        float2 v = t2v[(long long)s * 32 + lane];
        acc.x += v.x; acc.y += v.y;
    }
    float di = g_dinv[w];
    float2 bb = ((const float2*)b2)[lane];
    float2 r;
    r.x = fmaf(di, acc.x, bb.x);
    r.y = fmaf(di, acc.y, bb.y);
    ((float2*)out)[(long long)w * 32 + lane] = r;
}

// ---------------------------------------------------------------------------
extern "C" void kernel_launch(void* const* d_in, const int* in_sizes, int n_in,
                              void* d_out, int out_size) {
    const float* x  = (const float*)d_in[0];
    const void*  ei = d_in[1];
    const float* W1 = (const float*)d_in[2];
    const float* b1 = (const float*)d_in[3];
    const float* W2 = (const float*)d_in[4];
    const float* b2 = (const float*)d_in[5];
    float* out = (float*)d_out;

    int N = in_sizes[0] / C1;            // 50000
    long long E = in_sizes[1] / 2;       // 800000

    void *p_t1h = nullptr, *p_r = nullptr, *p_t2 = nullptr;
    cudaGetSymbolAddress(&p_t1h, g_t1h);
    cudaGetSymbolAddress(&p_r,   g_r);
    cudaGetSymbolAddress(&p_t2,  g_t2);

    // 1) Entire CSR build in one persistent kernel
    k_csr<<<CSR_BLOCKS, CSR_THREADS>>>(ei, N, E);

    // 2) GEMM1 -> t1h (fp16, dinv-scaled)
    int gg = (N + 127) / 128;
    k_gemm_tf32<C1, true><<<gg, 256>>>(x, W1, p_t1h, N);

    // 3) pull1 -> r
    long long warpThreads = (long long)N * 32;
    int gw = (int)((warpThreads + 255) / 256);
    k_pull1<<<gw, 256>>>(b1, N);

    // 4) GEMM2 -> t2 (fp32, dinv-scaled)
    k_gemm_tf32<C2, false><<<gg, 256>>>((const float*)p_r, W2, p_t2, N);

    // 5) pull2 -> out
    k_pull2<<<gw, 256>>>(b2, out, N);
}